// round 6
// baseline (speedup 1.0000x reference)
#include <cuda_runtime.h>
#include <math.h>

#define N_NODES 100000
#define N_EDGES 1250000
#define D 64
#define N_LAYERS 4

// ---- gemm kernel config ----
#define TPB 256                       // 8 warps
#define N_TILES 4                     // 4 tiles of 32 nodes; 2 warps (dim-halves) per tile
#define NPB (N_TILES * 32)            // 128 nodes per block
#define PITCH 129                     // odd pitch -> conflict-free sA[lane][k] reads
#define SMEM_A_FLOATS (NPB * PITCH)
#define SMEM_W_FLOATS (2 * D * D)
#define SMEM_BYTES ((SMEM_A_FLOATS + SMEM_W_FLOATS + D) * 4)

// ---- gather kernel config ----
#define GTPB 256                      // 8 warps x 4 subgroups = 32 nodes per block
#define GNPB 32

// ---- scan config ----
#define SBLK 1024
#define NSB ((N_NODES + SBLK - 1) / SBLK)   // 98

// ---------------- scratch (static device globals) ---------------------------
__device__ float g_buf0[N_NODES * D];
__device__ float g_buf1[N_NODES * D];
__device__ float g_agg[N_NODES * D];
__device__ int   g_counts[N_NODES];
__device__ int   g_rowptr[N_NODES + 1];
__device__ int   g_cursor[N_NODES];
__device__ int   g_csr[N_EDGES];
__device__ int   g_bsums[NSB];
__device__ int   g_total;
__device__ int   g_is64;

// ---------------- packed f32x2 helpers --------------------------------------
__device__ __forceinline__ unsigned long long pk(float x, float y) {
    unsigned long long r;
    asm("mov.b64 %0, {%1, %2};" : "=l"(r) : "f"(x), "f"(y));
    return r;
}
__device__ __forceinline__ void fma2(unsigned long long& d,
                                     unsigned long long a, unsigned long long b) {
    asm("fma.rn.f32x2 %0, %1, %2, %0;" : "+l"(d) : "l"(a), "l"(b));
}
__device__ __forceinline__ float2 upk(unsigned long long v) {
    float2 r;
    asm("mov.b64 {%0, %1}, %2;" : "=f"(r.x), "=f"(r.y) : "l"(v));
    return r;
}
__device__ __forceinline__ float4 max4(float4 a, float4 b) {
    a.x = fmaxf(a.x, b.x); a.y = fmaxf(a.y, b.y);
    a.z = fmaxf(a.z, b.z); a.w = fmaxf(a.w, b.w);
    return a;
}

// ---------------- init: zero counts + dtype detection ------------------------
__global__ void init_kernel(const void* __restrict__ edge_raw) {
    int i = blockIdx.x * blockDim.x + threadIdx.x;
    if (i < N_NODES) g_counts[i] = 0;
    if (i == 0) {
        const long long* e64 = (const long long*)edge_raw;
        int ok64 = 1;
        #pragma unroll 8
        for (int t = 0; t < 64; t++) {
            long long v = e64[t];
            if (v < 0 || v >= N_NODES) ok64 = 0;
        }
        g_is64 = ok64;
    }
}

__device__ __forceinline__ int load_edge(const void* edge_raw, long long idx, int is64) {
    if (is64) return (int)((const long long*)edge_raw)[idx];
    return ((const int*)edge_raw)[idx];
}

// ---------------- CSR build -------------------------------------------------
__global__ void histogram_kernel(const void* __restrict__ edge_raw) {
    int e = blockIdx.x * blockDim.x + threadIdx.x;
    if (e >= N_EDGES) return;
    int dst = load_edge(edge_raw, (long long)N_EDGES + e, g_is64);
    if (dst < 0 || dst >= N_NODES) return;
    atomicAdd(&g_counts[dst], 1);
}

__global__ __launch_bounds__(SBLK) void scan1_kernel() {
    __shared__ int wsum[32];
    int tid = threadIdx.x, lane = tid & 31, w = tid >> 5;
    int i = blockIdx.x * SBLK + tid;
    int v = (i < N_NODES) ? g_counts[i] : 0;
    int x = v;
    #pragma unroll
    for (int off = 1; off < 32; off <<= 1) {
        int y = __shfl_up_sync(0xffffffffu, x, off);
        if (lane >= off) x += y;
    }
    if (lane == 31) wsum[w] = x;
    __syncthreads();
    if (w == 0) {
        int s = wsum[lane];
        #pragma unroll
        for (int off = 1; off < 32; off <<= 1) {
            int y = __shfl_up_sync(0xffffffffu, s, off);
            if (lane >= off) s += y;
        }
        wsum[lane] = s;
    }
    __syncthreads();
    int incl = x + ((w > 0) ? wsum[w - 1] : 0);
    if (i < N_NODES) g_rowptr[i] = incl - v;
    if (tid == SBLK - 1) g_bsums[blockIdx.x] = incl;
}

__global__ void scan2_kernel() {
    __shared__ int wsum[4];
    int tid = threadIdx.x, lane = tid & 31, w = tid >> 5;
    int v = (tid < NSB) ? g_bsums[tid] : 0;
    int x = v;
    #pragma unroll
    for (int off = 1; off < 32; off <<= 1) {
        int y = __shfl_up_sync(0xffffffffu, x, off);
        if (lane >= off) x += y;
    }
    if (lane == 31) wsum[w] = x;
    __syncthreads();
    int wp = 0;
    for (int q = 0; q < w; q++) wp += wsum[q];
    int incl = x + wp;
    if (tid < NSB) g_bsums[tid] = incl - v;
    if (tid == 127) g_total = incl;
}

__global__ __launch_bounds__(SBLK) void scan3_kernel() {
    int i = blockIdx.x * SBLK + threadIdx.x;
    if (i < N_NODES) {
        int r = g_rowptr[i] + g_bsums[blockIdx.x];
        g_rowptr[i] = r;
        g_cursor[i] = r;
    }
    if (blockIdx.x == 0 && threadIdx.x == 0) g_rowptr[N_NODES] = g_total;
}

__global__ void scatter_kernel(const void* __restrict__ edge_raw) {
    int e = blockIdx.x * blockDim.x + threadIdx.x;
    if (e >= N_EDGES) return;
    int is64 = g_is64;
    int src = load_edge(edge_raw, e, is64);
    int dst = load_edge(edge_raw, (long long)N_EDGES + e, is64);
    if (src < 0 || src >= N_NODES || dst < 0 || dst >= N_NODES) return;
    int pos = atomicAdd(&g_cursor[dst], 1);
    if (pos >= 0 && pos < N_EDGES) g_csr[pos] = src;
}

// ---------------- gather: segment max-pool -> g_agg -------------------------
// 8-lane subgroup per node (lane covers 8 floats = 2 float4), 4 nodes/warp.
// 4-edge unroll: indices loaded up-front, then 8 independent float4 loads in
// flight per lane (MLP ~8) to hide L2 latency.
__global__ __launch_bounds__(GTPB) void gather_kernel(
    const float* __restrict__ x_ext, int in_mode)
{
    const float* h_in = (in_mode == 0) ? x_ext : ((in_mode == 1) ? g_buf0 : g_buf1);
    int tid = threadIdx.x;
    int warp = tid >> 5, lane = tid & 31;
    int sub = lane >> 3, dl = lane & 7;

    int node = blockIdx.x * GNPB + warp * 4 + sub;
    if (node >= N_NODES) return;
    int start = g_rowptr[node];
    int end   = g_rowptr[node + 1];

    float4 m0 = make_float4(-INFINITY, -INFINITY, -INFINITY, -INFINITY);
    float4 m1 = m0;
    int j = start;
    #pragma unroll 1
    for (; j + 4 <= end; j += 4) {
        int s0 = g_csr[j];
        int s1 = g_csr[j + 1];
        int s2 = g_csr[j + 2];
        int s3 = g_csr[j + 3];
        const float4* p0 = (const float4*)(h_in + (size_t)s0 * D) + dl * 2;
        const float4* p1 = (const float4*)(h_in + (size_t)s1 * D) + dl * 2;
        const float4* p2 = (const float4*)(h_in + (size_t)s2 * D) + dl * 2;
        const float4* p3 = (const float4*)(h_in + (size_t)s3 * D) + dl * 2;
        float4 a0 = p0[0], a1 = p0[1];
        float4 b0 = p1[0], b1 = p1[1];
        float4 c0 = p2[0], c1 = p2[1];
        float4 d0 = p3[0], d1 = p3[1];
        m0 = max4(m0, a0); m1 = max4(m1, a1);
        m0 = max4(m0, b0); m1 = max4(m1, b1);
        m0 = max4(m0, c0); m1 = max4(m1, c1);
        m0 = max4(m0, d0); m1 = max4(m1, d1);
    }
    if (j + 2 <= end) {
        int s0 = g_csr[j];
        int s1 = g_csr[j + 1];
        const float4* p0 = (const float4*)(h_in + (size_t)s0 * D) + dl * 2;
        const float4* p1 = (const float4*)(h_in + (size_t)s1 * D) + dl * 2;
        float4 a0 = p0[0], a1 = p0[1];
        float4 b0 = p1[0], b1 = p1[1];
        m0 = max4(m0, a0); m1 = max4(m1, a1);
        m0 = max4(m0, b0); m1 = max4(m1, b1);
        j += 2;
    }
    if (j < end) {
        int s0 = g_csr[j];
        const float4* p0 = (const float4*)(h_in + (size_t)s0 * D) + dl * 2;
        m0 = max4(m0, p0[0]);
        m1 = max4(m1, p0[1]);
    }
    if (start == end) {               // empty segment -> 0 (PyG)
        m0 = make_float4(0.f, 0.f, 0.f, 0.f);
        m1 = m0;
    }
    float4* arow = (float4*)(g_agg + (size_t)node * D);
    arow[dl * 2]     = m0;
    arow[dl * 2 + 1] = m1;
}

// ---------------- gemm: out = relu([agg|h] @ [Wl;Wr] + bl) -------------------
__global__ __launch_bounds__(TPB) void gemm_kernel(
    const float* __restrict__ x_ext, float* __restrict__ out_ext,
    const float* __restrict__ Wl, const float* __restrict__ bl,
    const float* __restrict__ Wr,
    int layer, int in_mode, int out_mode)
{
    extern __shared__ float smem[];
    float* sA = smem;                    // [128][129]: cols 0..63 agg, 64..127 self
    float* sW = smem + SMEM_A_FLOATS;    // [128][64]:  k<64 -> Wl, k>=64 -> Wr
    float* sB = sW + SMEM_W_FLOATS;

    const float* h_in  = (in_mode  == 0) ? x_ext  : ((in_mode  == 1) ? g_buf0 : g_buf1);
    float*       h_out = (out_mode == 0) ? out_ext : ((out_mode == 1) ? g_buf0 : g_buf1);

    int tid = threadIdx.x;
    int blockBase = blockIdx.x * NPB;
    {
        const float4* wl4 = (const float4*)(Wl + layer * D * D);
        const float4* wr4 = (const float4*)(Wr + layer * D * D);
        float4* sW4 = (float4*)sW;
        #pragma unroll
        for (int i = tid; i < D * D / 4; i += TPB) sW4[i] = wl4[i];
        #pragma unroll
        for (int i = tid; i < D * D / 4; i += TPB) sW4[D * D / 4 + i] = wr4[i];
        if (tid < D) sB[tid] = bl[layer * D + tid];
    }
    // stage A = [agg | h] (coalesced float4 global loads, scalar pitched stores)
    #pragma unroll 2
    for (int i = tid; i < NPB * (D / 4); i += TPB) {
        int row = i >> 4, c4 = i & 15;
        int node = blockBase + row;
        float4 va = make_float4(0.f, 0.f, 0.f, 0.f), vh = va;
        if (node < N_NODES) {
            va = ((const float4*)(g_agg + (size_t)node * D))[c4];
            vh = ((const float4*)(h_in  + (size_t)node * D))[c4];
        }
        float* arow = sA + row * PITCH;
        int o = c4 * 4;
        arow[o] = va.x; arow[o + 1] = va.y; arow[o + 2] = va.z; arow[o + 3] = va.w;
        arow[64 + o] = vh.x; arow[64 + o + 1] = vh.y;
        arow[64 + o + 2] = vh.z; arow[64 + o + 3] = vh.w;
    }
    __syncthreads();

    int warp = tid >> 5, lane = tid & 31;
    int tile = warp >> 1, half = warp & 1;
    int nl = tile * 32 + lane;
    int node = blockBase + nl;
    const float* arow = sA + nl * PITCH;
    const float* wbase = sW + half * 32;

    unsigned long long acc[16];
    {
        const float* bb = sB + half * 32;
        #pragma unroll
        for (int j = 0; j < 16; j++) acc[j] = pk(bb[2 * j], bb[2 * j + 1]);
    }
    #pragma unroll 4
    for (int k = 0; k < 2 * D; k++) {
        float a = arow[k];                         // conflict-free (pitch 129)
        unsigned long long aa = pk(a, a);
        const ulonglong2* w2 = (const ulonglong2*)(wbase + k * D);
        #pragma unroll
        for (int j = 0; j < 8; j++) {
            ulonglong2 w = w2[j];                  // LDS.128 broadcast
            fma2(acc[2 * j],     aa, w.x);
            fma2(acc[2 * j + 1], aa, w.y);
        }
    }
    if (node < N_NODES) {
        float4* orow = (float4*)(h_out + node * D + half * 32);
        #pragma unroll
        for (int j = 0; j < 8; j++) {
            float2 p0 = upk(acc[2 * j]);
            float2 p1 = upk(acc[2 * j + 1]);
            float4 o;
            o.x = fmaxf(p0.x, 0.0f); o.y = fmaxf(p0.y, 0.0f);
            o.z = fmaxf(p1.x, 0.0f); o.w = fmaxf(p1.y, 0.0f);
            orow[j] = o;
        }
    }
}

// ---------------- launch -----------------------------------------------------
extern "C" void kernel_launch(void* const* d_in, const int* in_sizes, int n_in,
                              void* d_out, int out_size) {
    const float* x  = nullptr;
    const void*  edge = nullptr;
    const float* Wl = nullptr;
    const float* Wr = nullptr;
    const float* bl = nullptr;
    for (int i = 0; i < n_in; i++) {
        int sz = in_sizes[i];
        if (sz == N_NODES * D)            x    = (const float*)d_in[i];
        else if (sz == 2 * N_EDGES)       edge = d_in[i];
        else if (sz == N_LAYERS * D * D) { if (!Wl) Wl = (const float*)d_in[i];
                                           else     Wr = (const float*)d_in[i]; }
        else if (sz == N_LAYERS * D)      bl   = (const float*)d_in[i];
    }
    float* out = (float*)d_out;

    static int smem_set = 0;
    if (!smem_set) {
        cudaFuncSetAttribute(gemm_kernel,
                             cudaFuncAttributeMaxDynamicSharedMemorySize, SMEM_BYTES);
        smem_set = 1;
    }

    init_kernel<<<(N_NODES + 255) / 256, 256>>>(edge);
    histogram_kernel<<<(N_EDGES + 255) / 256, 256>>>(edge);
    scan1_kernel<<<NSB, SBLK>>>();
    scan2_kernel<<<1, 128>>>();
    scan3_kernel<<<NSB, SBLK>>>();
    scatter_kernel<<<(N_EDGES + 255) / 256, 256>>>(edge);

    int gblocks = (N_NODES + GNPB - 1) / GNPB;
    int mblocks = (N_NODES + NPB - 1) / NPB;
    // ping-pong: x -> buf0 -> buf1 -> buf0 -> out
    const int im[4] = {0, 1, 2, 1};
    const int om[4] = {1, 2, 1, 0};
    for (int l = 0; l < N_LAYERS; l++) {
        gather_kernel<<<gblocks, GTPB>>>(x, im[l]);
        gemm_kernel<<<mblocks, TPB, SMEM_BYTES>>>(x, out, Wl, bl, Wr, l, im[l], om[l]);
    }
}

// round 7
// speedup vs baseline: 1.1932x; 1.1932x over previous
#include <cuda_runtime.h>
#include <cuda_fp16.h>
#include <math.h>

#define N_NODES 100000
#define N_EDGES 1250000
#define D 64
#define N_LAYERS 4

// ---- gemm kernel config ----
#define TPB 256                       // 8 warps
#define NPB 128                       // nodes per block
#define PITCH 129                     // odd pitch -> conflict-free sA[lane][k] reads
#define SMEM_A_FLOATS (NPB * PITCH)
#define SMEM_W_FLOATS (2 * D * D)
#define SMEM_BYTES ((SMEM_A_FLOATS + SMEM_W_FLOATS + D) * 4)

// ---- gather kernel config ----
#define GTPB 256                      // 8 warps x 4 subgroups = 32 nodes per block
#define GNPB 32

// ---- scan config ----
#define SBLK 1024
#define NSB ((N_NODES + SBLK - 1) / SBLK)   // 98

// ---------------- scratch (static device globals) ---------------------------
__device__ float  g_agg[N_NODES * D];       // fp32 agg (layer 1 only)
__device__ __half g_h16a[N_NODES * D];      // half intermediates (ping)
__device__ __half g_h16b[N_NODES * D];      // half intermediates (pong)
__device__ __half g_agg16[N_NODES * D];     // half agg (layers 2-4)
__device__ int    g_counts[N_NODES];
__device__ int    g_rowptr[N_NODES + 1];
__device__ int    g_cursor[N_NODES];
__device__ int    g_csr[N_EDGES];
__device__ int    g_bsums[NSB];
__device__ int    g_is64;

// ---------------- packed f32x2 helpers --------------------------------------
__device__ __forceinline__ unsigned long long pk(float x, float y) {
    unsigned long long r;
    asm("mov.b64 %0, {%1, %2};" : "=l"(r) : "f"(x), "f"(y));
    return r;
}
__device__ __forceinline__ void fma2(unsigned long long& d,
                                     unsigned long long a, unsigned long long b) {
    asm("fma.rn.f32x2 %0, %1, %2, %0;" : "+l"(d) : "l"(a), "l"(b));
}
__device__ __forceinline__ float2 upk(unsigned long long v) {
    float2 r;
    asm("mov.b64 {%0, %1}, %2;" : "=f"(r.x), "=f"(r.y) : "l"(v));
    return r;
}
__device__ __forceinline__ float4 max4(float4 a, float4 b) {
    a.x = fmaxf(a.x, b.x); a.y = fmaxf(a.y, b.y);
    a.z = fmaxf(a.z, b.z); a.w = fmaxf(a.w, b.w);
    return a;
}

// ---------------- init: zero counts + dtype detection ------------------------
__global__ void init_kernel(const void* __restrict__ edge_raw) {
    int i = blockIdx.x * blockDim.x + threadIdx.x;
    if (i < N_NODES) g_counts[i] = 0;
    if (i == 0) {
        const long long* e64 = (const long long*)edge_raw;
        int ok64 = 1;
        #pragma unroll 8
        for (int t = 0; t < 64; t++) {
            long long v = e64[t];
            if (v < 0 || v >= N_NODES) ok64 = 0;
        }
        g_is64 = ok64;
    }
}

__device__ __forceinline__ int load_edge(const void* edge_raw, long long idx, int is64) {
    if (is64) return (int)((const long long*)edge_raw)[idx];
    return ((const int*)edge_raw)[idx];
}

// ---------------- CSR build -------------------------------------------------
__global__ void histogram_kernel(const void* __restrict__ edge_raw) {
    int e = blockIdx.x * blockDim.x + threadIdx.x;
    if (e >= N_EDGES) return;
    int dst = load_edge(edge_raw, (long long)N_EDGES + e, g_is64);
    if (dst < 0 || dst >= N_NODES) return;
    atomicAdd(&g_counts[dst], 1);
}

__global__ __launch_bounds__(SBLK) void scan1_kernel() {
    __shared__ int wsum[32];
    int tid = threadIdx.x, lane = tid & 31, w = tid >> 5;
    int i = blockIdx.x * SBLK + tid;
    int v = (i < N_NODES) ? g_counts[i] : 0;
    int x = v;
    #pragma unroll
    for (int off = 1; off < 32; off <<= 1) {
        int y = __shfl_up_sync(0xffffffffu, x, off);
        if (lane >= off) x += y;
    }
    if (lane == 31) wsum[w] = x;
    __syncthreads();
    if (w == 0) {
        int s = wsum[lane];
        #pragma unroll
        for (int off = 1; off < 32; off <<= 1) {
            int y = __shfl_up_sync(0xffffffffu, s, off);
            if (lane >= off) s += y;
        }
        wsum[lane] = s;
    }
    __syncthreads();
    int incl = x + ((w > 0) ? wsum[w - 1] : 0);
    if (i < N_NODES) g_rowptr[i] = incl - v;
    if (tid == SBLK - 1) g_bsums[blockIdx.x] = incl;
}

// merged scan2+scan3: warp 0 rescans the 98 block totals locally, then all
// threads apply the block offset.
__global__ __launch_bounds__(SBLK) void scan3_kernel() {
    __shared__ int sExcl[NSB];
    __shared__ int sTot;
    int tid = threadIdx.x;
    if (tid < 32) {
        int carry = 0;
        #pragma unroll
        for (int base = 0; base < NSB; base += 32) {
            int idx = base + tid;
            int v = (idx < NSB) ? g_bsums[idx] : 0;
            int x = v;
            #pragma unroll
            for (int off = 1; off < 32; off <<= 1) {
                int y = __shfl_up_sync(0xffffffffu, x, off);
                if (tid >= off) x += y;
            }
            if (idx < NSB) sExcl[idx] = carry + x - v;
            carry += __shfl_sync(0xffffffffu, x, 31);
        }
        if (tid == 0) sTot = carry;
    }
    __syncthreads();
    int i = blockIdx.x * SBLK + tid;
    if (i < N_NODES) {
        int r = g_rowptr[i] + sExcl[blockIdx.x];
        g_rowptr[i] = r;
        g_cursor[i] = r;
    }
    if (blockIdx.x == 0 && tid == 0) g_rowptr[N_NODES] = sTot;
}

__global__ void scatter_kernel(const void* __restrict__ edge_raw) {
    int e = blockIdx.x * blockDim.x + threadIdx.x;
    if (e >= N_EDGES) return;
    int is64 = g_is64;
    int src = load_edge(edge_raw, e, is64);
    int dst = load_edge(edge_raw, (long long)N_EDGES + e, is64);
    if (src < 0 || src >= N_NODES || dst < 0 || dst >= N_NODES) return;
    int pos = atomicAdd(&g_cursor[dst], 1);
    if (pos >= 0 && pos < N_EDGES) g_csr[pos] = src;
}

// ---------------- gather fp32 (layer 1): x -> g_agg --------------------------
__global__ __launch_bounds__(GTPB) void gather32_kernel(
    const float* __restrict__ h_in, float* __restrict__ agg_out)
{
    int tid = threadIdx.x;
    int warp = tid >> 5, lane = tid & 31;
    int sub = lane >> 3, dl = lane & 7;

    int node = blockIdx.x * GNPB + warp * 4 + sub;
    if (node >= N_NODES) return;
    int start = g_rowptr[node];
    int end   = g_rowptr[node + 1];

    float4 m0 = make_float4(-INFINITY, -INFINITY, -INFINITY, -INFINITY);
    float4 m1 = m0;
    int j = start;
    #pragma unroll 1
    for (; j + 2 <= end; j += 2) {
        int s0 = g_csr[j];
        int s1 = g_csr[j + 1];
        const float4* p0 = (const float4*)(h_in + (size_t)s0 * D) + dl * 2;
        const float4* p1 = (const float4*)(h_in + (size_t)s1 * D) + dl * 2;
        float4 a0 = p0[0], a1 = p0[1];
        float4 b0 = p1[0], b1 = p1[1];
        m0 = max4(m0, a0); m1 = max4(m1, a1);
        m0 = max4(m0, b0); m1 = max4(m1, b1);
    }
    if (j < end) {
        int s0 = g_csr[j];
        const float4* p0 = (const float4*)(h_in + (size_t)s0 * D) + dl * 2;
        m0 = max4(m0, p0[0]);
        m1 = max4(m1, p0[1]);
    }
    if (start == end) {
        m0 = make_float4(0.f, 0.f, 0.f, 0.f);
        m1 = m0;
    }
    float4* arow = (float4*)(agg_out + (size_t)node * D);
    arow[dl * 2]     = m0;
    arow[dl * 2 + 1] = m1;
}

// ---------------- gather fp16 (layers 2-4): h16 -> g_agg16 -------------------
// One LDG.128 per lane per edge (row is 128 B). 4-edge unroll.
__global__ __launch_bounds__(GTPB) void gather16_kernel(
    const __half* __restrict__ h_in, __half* __restrict__ agg_out)
{
    int tid = threadIdx.x;
    int warp = tid >> 5, lane = tid & 31;
    int sub = lane >> 3, dl = lane & 7;

    int node = blockIdx.x * GNPB + warp * 4 + sub;
    if (node >= N_NODES) return;
    int start = g_rowptr[node];
    int end   = g_rowptr[node + 1];

    const __half neginf = __ushort_as_half((unsigned short)0xFC00);
    __half2 m0 = __half2half2(neginf), m1 = m0, m2 = m0, m3 = m0;

    int j = start;
    #pragma unroll 1
    for (; j + 4 <= end; j += 4) {
        int s0 = g_csr[j];
        int s1 = g_csr[j + 1];
        int s2 = g_csr[j + 2];
        int s3 = g_csr[j + 3];
        uint4 v0 = *(const uint4*)(h_in + (size_t)s0 * D + dl * 8);
        uint4 v1 = *(const uint4*)(h_in + (size_t)s1 * D + dl * 8);
        uint4 v2 = *(const uint4*)(h_in + (size_t)s2 * D + dl * 8);
        uint4 v3 = *(const uint4*)(h_in + (size_t)s3 * D + dl * 8);
        m0 = __hmax2(m0, *(__half2*)&v0.x); m1 = __hmax2(m1, *(__half2*)&v0.y);
        m2 = __hmax2(m2, *(__half2*)&v0.z); m3 = __hmax2(m3, *(__half2*)&v0.w);
        m0 = __hmax2(m0, *(__half2*)&v1.x); m1 = __hmax2(m1, *(__half2*)&v1.y);
        m2 = __hmax2(m2, *(__half2*)&v1.z); m3 = __hmax2(m3, *(__half2*)&v1.w);
        m0 = __hmax2(m0, *(__half2*)&v2.x); m1 = __hmax2(m1, *(__half2*)&v2.y);
        m2 = __hmax2(m2, *(__half2*)&v2.z); m3 = __hmax2(m3, *(__half2*)&v2.w);
        m0 = __hmax2(m0, *(__half2*)&v3.x); m1 = __hmax2(m1, *(__half2*)&v3.y);
        m2 = __hmax2(m2, *(__half2*)&v3.z); m3 = __hmax2(m3, *(__half2*)&v3.w);
    }
    if (j + 2 <= end) {
        int s0 = g_csr[j];
        int s1 = g_csr[j + 1];
        uint4 v0 = *(const uint4*)(h_in + (size_t)s0 * D + dl * 8);
        uint4 v1 = *(const uint4*)(h_in + (size_t)s1 * D + dl * 8);
        m0 = __hmax2(m0, *(__half2*)&v0.x); m1 = __hmax2(m1, *(__half2*)&v0.y);
        m2 = __hmax2(m2, *(__half2*)&v0.z); m3 = __hmax2(m3, *(__half2*)&v0.w);
        m0 = __hmax2(m0, *(__half2*)&v1.x); m1 = __hmax2(m1, *(__half2*)&v1.y);
        m2 = __hmax2(m2, *(__half2*)&v1.z); m3 = __hmax2(m3, *(__half2*)&v1.w);
        j += 2;
    }
    if (j < end) {
        int s0 = g_csr[j];
        uint4 v0 = *(const uint4*)(h_in + (size_t)s0 * D + dl * 8);
        m0 = __hmax2(m0, *(__half2*)&v0.x); m1 = __hmax2(m1, *(__half2*)&v0.y);
        m2 = __hmax2(m2, *(__half2*)&v0.z); m3 = __hmax2(m3, *(__half2*)&v0.w);
    }
    if (start == end) {
        __half2 z = __half2half2(__ushort_as_half((unsigned short)0));
        m0 = z; m1 = z; m2 = z; m3 = z;
    }
    uint4 o;
    o.x = *(unsigned*)&m0; o.y = *(unsigned*)&m1;
    o.z = *(unsigned*)&m2; o.w = *(unsigned*)&m3;
    *(uint4*)(agg_out + (size_t)node * D + dl * 8) = o;
}

// ---------------- gemm: out = relu([agg|h] @ [Wl;Wr] + bl) -------------------
template <int IN16, int OUT16>
__global__ __launch_bounds__(TPB) void gemm_kernel(
    const void* __restrict__ aggp, const void* __restrict__ hp,
    void* __restrict__ outp,
    const float* __restrict__ Wl, const float* __restrict__ bl,
    const float* __restrict__ Wr, int layer)
{
    extern __shared__ float smem[];
    float* sA = smem;                    // [128][129]: cols 0..63 agg, 64..127 self
    float* sW = smem + SMEM_A_FLOATS;    // [128][64]:  k<64 -> Wl, k>=64 -> Wr
    float* sB = sW + SMEM_W_FLOATS;

    int tid = threadIdx.x;
    int blockBase = blockIdx.x * NPB;
    {
        const float4* wl4 = (const float4*)(Wl + layer * D * D);
        const float4* wr4 = (const float4*)(Wr + layer * D * D);
        float4* sW4 = (float4*)sW;
        #pragma unroll
        for (int i = tid; i < D * D / 4; i += TPB) sW4[i] = wl4[i];
        #pragma unroll
        for (int i = tid; i < D * D / 4; i += TPB) sW4[D * D / 4 + i] = wr4[i];
        if (tid < D) sB[tid] = bl[layer * D + tid];
    }
    // stage A = [agg | h]
    if (IN16) {
        const __half* ag = (const __half*)aggp;
        const __half* hh = (const __half*)hp;
        #pragma unroll 2
        for (int i = tid; i < NPB * 8; i += TPB) {
            int row = i >> 3, c = i & 7;
            int node = blockBase + row;
            uint4 va = make_uint4(0, 0, 0, 0), vh = va;
            if (node < N_NODES) {
                va = ((const uint4*)(ag + (size_t)node * D))[c];
                vh = ((const uint4*)(hh + (size_t)node * D))[c];
            }
            float* arow = sA + row * PITCH;
            int o = c * 8;
            float2 f;
            f = __half22float2(*(__half2*)&va.x); arow[o + 0] = f.x; arow[o + 1] = f.y;
            f = __half22float2(*(__half2*)&va.y); arow[o + 2] = f.x; arow[o + 3] = f.y;
            f = __half22float2(*(__half2*)&va.z); arow[o + 4] = f.x; arow[o + 5] = f.y;
            f = __half22float2(*(__half2*)&va.w); arow[o + 6] = f.x; arow[o + 7] = f.y;
            f = __half22float2(*(__half2*)&vh.x); arow[64 + o + 0] = f.x; arow[64 + o + 1] = f.y;
            f = __half22float2(*(__half2*)&vh.y); arow[64 + o + 2] = f.x; arow[64 + o + 3] = f.y;
            f = __half22float2(*(__half2*)&vh.z); arow[64 + o + 4] = f.x; arow[64 + o + 5] = f.y;
            f = __half22float2(*(__half2*)&vh.w); arow[64 + o + 6] = f.x; arow[64 + o + 7] = f.y;
        }
    } else {
        const float* ag = (const float*)aggp;
        const float* hh = (const float*)hp;
        #pragma unroll 2
        for (int i = tid; i < NPB * 16; i += TPB) {
            int row = i >> 4, c4 = i & 15;
            int node = blockBase + row;
            float4 va = make_float4(0.f, 0.f, 0.f, 0.f), vh = va;
            if (node < N_NODES) {
                va = ((const float4*)(ag + (size_t)node * D))[c4];
                vh = ((const float4*)(hh + (size_t)node * D))[c4];
            }
            float* arow = sA + row * PITCH;
            int o = c4 * 4;
            arow[o] = va.x; arow[o + 1] = va.y; arow[o + 2] = va.z; arow[o + 3] = va.w;
            arow[64 + o] = vh.x; arow[64 + o + 1] = vh.y;
            arow[64 + o + 2] = vh.z; arow[64 + o + 3] = vh.w;
        }
    }
    __syncthreads();

    int warp = tid >> 5, lane = tid & 31;
    int tile = warp >> 1, half = warp & 1;
    int nl = tile * 32 + lane;
    int node = blockBase + nl;
    const float* arow = sA + nl * PITCH;
    const float* wbase = sW + half * 32;

    unsigned long long acc[16];
    {
        const float* bb = sB + half * 32;
        #pragma unroll
        for (int j = 0; j < 16; j++) acc[j] = pk(bb[2 * j], bb[2 * j + 1]);
    }
    #pragma unroll 4
    for (int k = 0; k < 2 * D; k++) {
        float a = arow[k];                         // conflict-free (pitch 129)
        unsigned long long aa = pk(a, a);
        const ulonglong2* w2 = (const ulonglong2*)(wbase + k * D);
        #pragma unroll
        for (int j = 0; j < 8; j++) {
            ulonglong2 w = w2[j];                  // LDS.128 broadcast
            fma2(acc[2 * j],     aa, w.x);
            fma2(acc[2 * j + 1], aa, w.y);
        }
    }
    if (node < N_NODES) {
        if (OUT16) {
            uint4* o16 = (uint4*)((__half*)outp + (size_t)node * D + half * 32);
            #pragma unroll
            for (int q = 0; q < 4; q++) {
                uint4 w;
                float2 p0 = upk(acc[4 * q + 0]);
                float2 p1 = upk(acc[4 * q + 1]);
                float2 p2 = upk(acc[4 * q + 2]);
                float2 p3 = upk(acc[4 * q + 3]);
                __half2 h0 = __floats2half2_rn(fmaxf(p0.x, 0.f), fmaxf(p0.y, 0.f));
                __half2 h1 = __floats2half2_rn(fmaxf(p1.x, 0.f), fmaxf(p1.y, 0.f));
                __half2 h2 = __floats2half2_rn(fmaxf(p2.x, 0.f), fmaxf(p2.y, 0.f));
                __half2 h3 = __floats2half2_rn(fmaxf(p3.x, 0.f), fmaxf(p3.y, 0.f));
                w.x = *(unsigned*)&h0; w.y = *(unsigned*)&h1;
                w.z = *(unsigned*)&h2; w.w = *(unsigned*)&h3;
                o16[q] = w;
            }
        } else {
            float4* orow = (float4*)((float*)outp + (size_t)node * D + half * 32);
            #pragma unroll
            for (int j = 0; j < 8; j++) {
                float2 p0 = upk(acc[2 * j]);
                float2 p1 = upk(acc[2 * j + 1]);
                float4 o;
                o.x = fmaxf(p0.x, 0.0f); o.y = fmaxf(p0.y, 0.0f);
                o.z = fmaxf(p1.x, 0.0f); o.w = fmaxf(p1.y, 0.0f);
                orow[j] = o;
            }
        }
    }
}

// ---------------- launch -----------------------------------------------------
extern "C" void kernel_launch(void* const* d_in, const int* in_sizes, int n_in,
                              void* d_out, int out_size) {
    const float* x  = nullptr;
    const void*  edge = nullptr;
    const float* Wl = nullptr;
    const float* Wr = nullptr;
    const float* bl = nullptr;
    for (int i = 0; i < n_in; i++) {
        int sz = in_sizes[i];
        if (sz == N_NODES * D)            x    = (const float*)d_in[i];
        else if (sz == 2 * N_EDGES)       edge = d_in[i];
        else if (sz == N_LAYERS * D * D) { if (!Wl) Wl = (const float*)d_in[i];
                                           else     Wr = (const float*)d_in[i]; }
        else if (sz == N_LAYERS * D)      bl   = (const float*)d_in[i];
    }
    float* out = (float*)d_out;

    static int smem_set = 0;
    if (!smem_set) {
        cudaFuncSetAttribute(gemm_kernel<0, 1>,
                             cudaFuncAttributeMaxDynamicSharedMemorySize, SMEM_BYTES);
        cudaFuncSetAttribute(gemm_kernel<1, 1>,
                             cudaFuncAttributeMaxDynamicSharedMemorySize, SMEM_BYTES);
        cudaFuncSetAttribute(gemm_kernel<1, 0>,
                             cudaFuncAttributeMaxDynamicSharedMemorySize, SMEM_BYTES);
        smem_set = 1;
    }

    init_kernel<<<(N_NODES + 255) / 256, 256>>>(edge);
    histogram_kernel<<<(N_EDGES + 255) / 256, 256>>>(edge);
    scan1_kernel<<<NSB, SBLK>>>();
    scan3_kernel<<<NSB, SBLK>>>();
    scatter_kernel<<<(N_EDGES + 255) / 256, 256>>>(edge);

    int gblocks = (N_NODES + GNPB - 1) / GNPB;
    int mblocks = (N_NODES + NPB - 1) / NPB;

    __half* h16a = nullptr; __half* h16b = nullptr;
    __half* agg16 = nullptr; float* agg32 = nullptr;
    cudaGetSymbolAddress((void**)&h16a, g_h16a);
    cudaGetSymbolAddress((void**)&h16b, g_h16b);
    cudaGetSymbolAddress((void**)&agg16, g_agg16);
    cudaGetSymbolAddress((void**)&agg32, g_agg);

    // layer 1: fp32 in, fp16 out
    gather32_kernel<<<gblocks, GTPB>>>(x, agg32);
    gemm_kernel<0, 1><<<mblocks, TPB, SMEM_BYTES>>>(agg32, x, h16a, Wl, bl, Wr, 0);
    // layer 2: fp16 in/out
    gather16_kernel<<<gblocks, GTPB>>>(h16a, agg16);
    gemm_kernel<1, 1><<<mblocks, TPB, SMEM_BYTES>>>(agg16, h16a, h16b, Wl, bl, Wr, 1);
    // layer 3: fp16 in/out
    gather16_kernel<<<gblocks, GTPB>>>(h16b, agg16);
    gemm_kernel<1, 1><<<mblocks, TPB, SMEM_BYTES>>>(agg16, h16b, h16a, Wl, bl, Wr, 2);
    // layer 4: fp16 in, fp32 out
    gather16_kernel<<<gblocks, GTPB>>>(h16a, agg16);
    gemm_kernel<1, 0><<<mblocks, TPB, SMEM_BYTES>>>(agg16, h16a, out, Wl, bl, Wr, 3);
}

// round 8
// speedup vs baseline: 1.2173x; 1.0202x over previous
#include <cuda_runtime.h>
#include <cuda_fp16.h>
#include <math.h>

#define N_NODES 100000
#define N_EDGES 1250000
#define D 64
#define N_LAYERS 4

// ---- gemm kernel config ----
#define TPB 256                       // 8 warps
#define NPB 128                       // nodes per block
#define PITCH 129                     // odd pitch -> conflict-free sA[lane][k] reads
#define SMEM_A_FLOATS (NPB * PITCH)
#define SMEM_W_FLOATS (2 * D * D)
#define SMEM_BYTES ((SMEM_A_FLOATS + SMEM_W_FLOATS + D) * 4)

// ---- gather kernel config ----
#define GTPB 256                      // 8 warps x 4 subgroups = 32 nodes per block
#define GNPB 32

// ---- scan config ----
#define SBLK 1024
#define NSB ((N_NODES + SBLK - 1) / SBLK)   // 98

// ---------------- scratch (static device globals) ---------------------------
__device__ __half g_x16[N_NODES * D];       // fp16 copy of input x
__device__ __half g_h16a[N_NODES * D];      // half intermediates (ping)
__device__ __half g_h16b[N_NODES * D];      // half intermediates (pong)
__device__ __half g_agg16[N_NODES * D];     // half agg
__device__ int    g_counts[N_NODES];
__device__ int    g_rowptr[N_NODES + 1];
__device__ int    g_cursor[N_NODES];
__device__ int    g_csr[N_EDGES];
__device__ int    g_bsums[NSB];
__device__ int    g_is64;

// ---------------- packed f32x2 helpers --------------------------------------
__device__ __forceinline__ unsigned long long pk(float x, float y) {
    unsigned long long r;
    asm("mov.b64 %0, {%1, %2};" : "=l"(r) : "f"(x), "f"(y));
    return r;
}
__device__ __forceinline__ void fma2(unsigned long long& d,
                                     unsigned long long a, unsigned long long b) {
    asm("fma.rn.f32x2 %0, %1, %2, %0;" : "+l"(d) : "l"(a), "l"(b));
}
__device__ __forceinline__ float2 upk(unsigned long long v) {
    float2 r;
    asm("mov.b64 {%0, %1}, %2;" : "=f"(r.x), "=f"(r.y) : "l"(v));
    return r;
}

// ---------------- init: zero counts + dtype detection ------------------------
__global__ void init_kernel(const void* __restrict__ edge_raw) {
    int i = blockIdx.x * blockDim.x + threadIdx.x;
    if (i < N_NODES) g_counts[i] = 0;
    if (i == 0) {
        const long long* e64 = (const long long*)edge_raw;
        int ok64 = 1;
        #pragma unroll 8
        for (int t = 0; t < 64; t++) {
            long long v = e64[t];
            if (v < 0 || v >= N_NODES) ok64 = 0;
        }
        g_is64 = ok64;
    }
}

// ---------------- x -> fp16 conversion ---------------------------------------
__global__ void cvt16_kernel(const float* __restrict__ x) {
    int i = blockIdx.x * blockDim.x + threadIdx.x;   // one half2 per thread
    if (i >= N_NODES * D / 2) return;
    float2 v = ((const float2*)x)[i];
    ((__half2*)g_x16)[i] = __floats2half2_rn(v.x, v.y);
}

__device__ __forceinline__ int load_edge(const void* edge_raw, long long idx, int is64) {
    if (is64) return (int)((const long long*)edge_raw)[idx];
    return ((const int*)edge_raw)[idx];
}

// ---------------- CSR build -------------------------------------------------
__global__ void histogram_kernel(const void* __restrict__ edge_raw) {
    int e = blockIdx.x * blockDim.x + threadIdx.x;
    if (e >= N_EDGES) return;
    int dst = load_edge(edge_raw, (long long)N_EDGES + e, g_is64);
    if (dst < 0 || dst >= N_NODES) return;
    atomicAdd(&g_counts[dst], 1);
}

__global__ __launch_bounds__(SBLK) void scan1_kernel() {
    __shared__ int wsum[32];
    int tid = threadIdx.x, lane = tid & 31, w = tid >> 5;
    int i = blockIdx.x * SBLK + tid;
    int v = (i < N_NODES) ? g_counts[i] : 0;
    int x = v;
    #pragma unroll
    for (int off = 1; off < 32; off <<= 1) {
        int y = __shfl_up_sync(0xffffffffu, x, off);
        if (lane >= off) x += y;
    }
    if (lane == 31) wsum[w] = x;
    __syncthreads();
    if (w == 0) {
        int s = wsum[lane];
        #pragma unroll
        for (int off = 1; off < 32; off <<= 1) {
            int y = __shfl_up_sync(0xffffffffu, s, off);
            if (lane >= off) s += y;
        }
        wsum[lane] = s;
    }
    __syncthreads();
    int incl = x + ((w > 0) ? wsum[w - 1] : 0);
    if (i < N_NODES) g_rowptr[i] = incl - v;
    if (tid == SBLK - 1) g_bsums[blockIdx.x] = incl;
}

// merged scan2+scan3
__global__ __launch_bounds__(SBLK) void scan3_kernel() {
    __shared__ int sExcl[NSB];
    __shared__ int sTot;
    int tid = threadIdx.x;
    if (tid < 32) {
        int carry = 0;
        #pragma unroll
        for (int base = 0; base < NSB; base += 32) {
            int idx = base + tid;
            int v = (idx < NSB) ? g_bsums[idx] : 0;
            int x = v;
            #pragma unroll
            for (int off = 1; off < 32; off <<= 1) {
                int y = __shfl_up_sync(0xffffffffu, x, off);
                if (tid >= off) x += y;
            }
            if (idx < NSB) sExcl[idx] = carry + x - v;
            carry += __shfl_sync(0xffffffffu, x, 31);
        }
        if (tid == 0) sTot = carry;
    }
    __syncthreads();
    int i = blockIdx.x * SBLK + tid;
    if (i < N_NODES) {
        int r = g_rowptr[i] + sExcl[blockIdx.x];
        g_rowptr[i] = r;
        g_cursor[i] = r;
    }
    if (blockIdx.x == 0 && tid == 0) g_rowptr[N_NODES] = sTot;
}

__global__ void scatter_kernel(const void* __restrict__ edge_raw) {
    int e = blockIdx.x * blockDim.x + threadIdx.x;
    if (e >= N_EDGES) return;
    int is64 = g_is64;
    int src = load_edge(edge_raw, e, is64);
    int dst = load_edge(edge_raw, (long long)N_EDGES + e, is64);
    if (src < 0 || src >= N_NODES || dst < 0 || dst >= N_NODES) return;
    int pos = atomicAdd(&g_cursor[dst], 1);
    if (pos >= 0 && pos < N_EDGES) g_csr[pos] = src;
}

// ---------------- gather fp16: h16 -> agg16 ----------------------------------
// 8-lane subgroup per node; one LDG.128 per lane per edge; 4-edge unroll.
__global__ __launch_bounds__(GTPB) void gather16_kernel(
    const __half* __restrict__ h_in, __half* __restrict__ agg_out)
{
    int tid = threadIdx.x;
    int warp = tid >> 5, lane = tid & 31;
    int sub = lane >> 3, dl = lane & 7;

    int node = blockIdx.x * GNPB + warp * 4 + sub;
    if (node >= N_NODES) return;
    int start = g_rowptr[node];
    int end   = g_rowptr[node + 1];

    const __half neginf = __ushort_as_half((unsigned short)0xFC00);
    __half2 m0 = __half2half2(neginf), m1 = m0, m2 = m0, m3 = m0;

    int j = start;
    #pragma unroll 1
    for (; j + 4 <= end; j += 4) {
        int s0 = g_csr[j];
        int s1 = g_csr[j + 1];
        int s2 = g_csr[j + 2];
        int s3 = g_csr[j + 3];
        uint4 v0 = *(const uint4*)(h_in + (size_t)s0 * D + dl * 8);
        uint4 v1 = *(const uint4*)(h_in + (size_t)s1 * D + dl * 8);
        uint4 v2 = *(const uint4*)(h_in + (size_t)s2 * D + dl * 8);
        uint4 v3 = *(const uint4*)(h_in + (size_t)s3 * D + dl * 8);
        m0 = __hmax2(m0, *(__half2*)&v0.x); m1 = __hmax2(m1, *(__half2*)&v0.y);
        m2 = __hmax2(m2, *(__half2*)&v0.z); m3 = __hmax2(m3, *(__half2*)&v0.w);
        m0 = __hmax2(m0, *(__half2*)&v1.x); m1 = __hmax2(m1, *(__half2*)&v1.y);
        m2 = __hmax2(m2, *(__half2*)&v1.z); m3 = __hmax2(m3, *(__half2*)&v1.w);
        m0 = __hmax2(m0, *(__half2*)&v2.x); m1 = __hmax2(m1, *(__half2*)&v2.y);
        m2 = __hmax2(m2, *(__half2*)&v2.z); m3 = __hmax2(m3, *(__half2*)&v2.w);
        m0 = __hmax2(m0, *(__half2*)&v3.x); m1 = __hmax2(m1, *(__half2*)&v3.y);
        m2 = __hmax2(m2, *(__half2*)&v3.z); m3 = __hmax2(m3, *(__half2*)&v3.w);
    }
    if (j + 2 <= end) {
        int s0 = g_csr[j];
        int s1 = g_csr[j + 1];
        uint4 v0 = *(const uint4*)(h_in + (size_t)s0 * D + dl * 8);
        uint4 v1 = *(const uint4*)(h_in + (size_t)s1 * D + dl * 8);
        m0 = __hmax2(m0, *(__half2*)&v0.x); m1 = __hmax2(m1, *(__half2*)&v0.y);
        m2 = __hmax2(m2, *(__half2*)&v0.z); m3 = __hmax2(m3, *(__half2*)&v0.w);
        m0 = __hmax2(m0, *(__half2*)&v1.x); m1 = __hmax2(m1, *(__half2*)&v1.y);
        m2 = __hmax2(m2, *(__half2*)&v1.z); m3 = __hmax2(m3, *(__half2*)&v1.w);
        j += 2;
    }
    if (j < end) {
        int s0 = g_csr[j];
        uint4 v0 = *(const uint4*)(h_in + (size_t)s0 * D + dl * 8);
        m0 = __hmax2(m0, *(__half2*)&v0.x); m1 = __hmax2(m1, *(__half2*)&v0.y);
        m2 = __hmax2(m2, *(__half2*)&v0.z); m3 = __hmax2(m3, *(__half2*)&v0.w);
    }
    if (start == end) {
        __half2 z = __half2half2(__ushort_as_half((unsigned short)0));
        m0 = z; m1 = z; m2 = z; m3 = z;
    }
    uint4 o;
    o.x = *(unsigned*)&m0; o.y = *(unsigned*)&m1;
    o.z = *(unsigned*)&m2; o.w = *(unsigned*)&m3;
    *(uint4*)(agg_out + (size_t)node * D + dl * 8) = o;
}

// ---------------- gemm: out = relu([agg|h] @ [Wl;Wr] + bl) -------------------
template <int OUT16>
__global__ __launch_bounds__(TPB) void gemm_kernel(
    const __half* __restrict__ ag, const __half* __restrict__ hh,
    void* __restrict__ outp,
    const float* __restrict__ Wl, const float* __restrict__ bl,
    const float* __restrict__ Wr, int layer)
{
    extern __shared__ float smem[];
    float* sA = smem;                    // [128][129]: cols 0..63 agg, 64..127 self
    float* sW = smem + SMEM_A_FLOATS;    // [128][64]:  k<64 -> Wl, k>=64 -> Wr
    float* sB = sW + SMEM_W_FLOATS;

    int tid = threadIdx.x;
    int blockBase = blockIdx.x * NPB;
    {
        const float4* wl4 = (const float4*)(Wl + layer * D * D);
        const float4* wr4 = (const float4*)(Wr + layer * D * D);
        float4* sW4 = (float4*)sW;
        #pragma unroll
        for (int i = tid; i < D * D / 4; i += TPB) sW4[i] = wl4[i];
        #pragma unroll
        for (int i = tid; i < D * D / 4; i += TPB) sW4[D * D / 4 + i] = wr4[i];
        if (tid < D) sB[tid] = bl[layer * D + tid];
    }
    // stage A = [agg | h] (fp16 -> fp32)
    #pragma unroll 2
    for (int i = tid; i < NPB * 8; i += TPB) {
        int row = i >> 3, c = i & 7;
        int node = blockBase + row;
        uint4 va = make_uint4(0, 0, 0, 0), vh = va;
        if (node < N_NODES) {
            va = ((const uint4*)(ag + (size_t)node * D))[c];
            vh = ((const uint4*)(hh + (size_t)node * D))[c];
        }
        float* arow = sA + row * PITCH;
        int o = c * 8;
        float2 f;
        f = __half22float2(*(__half2*)&va.x); arow[o + 0] = f.x; arow[o + 1] = f.y;
        f = __half22float2(*(__half2*)&va.y); arow[o + 2] = f.x; arow[o + 3] = f.y;
        f = __half22float2(*(__half2*)&va.z); arow[o + 4] = f.x; arow[o + 5] = f.y;
        f = __half22float2(*(__half2*)&va.w); arow[o + 6] = f.x; arow[o + 7] = f.y;
        f = __half22float2(*(__half2*)&vh.x); arow[64 + o + 0] = f.x; arow[64 + o + 1] = f.y;
        f = __half22float2(*(__half2*)&vh.y); arow[64 + o + 2] = f.x; arow[64 + o + 3] = f.y;
        f = __half22float2(*(__half2*)&vh.z); arow[64 + o + 4] = f.x; arow[64 + o + 5] = f.y;
        f = __half22float2(*(__half2*)&vh.w); arow[64 + o + 6] = f.x; arow[64 + o + 7] = f.y;
    }
    __syncthreads();

    int warp = tid >> 5, lane = tid & 31;
    int tile = warp >> 1, half = warp & 1;
    int nl = tile * 32 + lane;
    int node = blockBase + nl;
    const float* arow = sA + nl * PITCH;
    const float* wbase = sW + half * 32;

    unsigned long long acc[16];
    {
        const float* bb = sB + half * 32;
        #pragma unroll
        for (int j = 0; j < 16; j++) acc[j] = pk(bb[2 * j], bb[2 * j + 1]);
    }
    #pragma unroll 4
    for (int k = 0; k < 2 * D; k++) {
        float a = arow[k];                         // conflict-free (pitch 129)
        unsigned long long aa = pk(a, a);
        const ulonglong2* w2 = (const ulonglong2*)(wbase + k * D);
        #pragma unroll
        for (int j = 0; j < 8; j++) {
            ulonglong2 w = w2[j];                  // LDS.128 broadcast
            fma2(acc[2 * j],     aa, w.x);
            fma2(acc[2 * j + 1], aa, w.y);
        }
    }
    if (node < N_NODES) {
        if (OUT16) {
            uint4* o16 = (uint4*)((__half*)outp + (size_t)node * D + half * 32);
            #pragma unroll
            for (int q = 0; q < 4; q++) {
                uint4 w;
                float2 p0 = upk(acc[4 * q + 0]);
                float2 p1 = upk(acc[4 * q + 1]);
                float2 p2 = upk(acc[4 * q + 2]);
                float2 p3 = upk(acc[4 * q + 3]);
                __half2 h0 = __floats2half2_rn(fmaxf(p0.x, 0.f), fmaxf(p0.y, 0.f));
                __half2 h1 = __floats2half2_rn(fmaxf(p1.x, 0.f), fmaxf(p1.y, 0.f));
                __half2 h2 = __floats2half2_rn(fmaxf(p2.x, 0.f), fmaxf(p2.y, 0.f));
                __half2 h3 = __floats2half2_rn(fmaxf(p3.x, 0.f), fmaxf(p3.y, 0.f));
                w.x = *(unsigned*)&h0; w.y = *(unsigned*)&h1;
                w.z = *(unsigned*)&h2; w.w = *(unsigned*)&h3;
                o16[q] = w;
            }
        } else {
            float4* orow = (float4*)((float*)outp + (size_t)node * D + half * 32);
            #pragma unroll
            for (int j = 0; j < 8; j++) {
                float2 p0 = upk(acc[2 * j]);
                float2 p1 = upk(acc[2 * j + 1]);
                float4 o;
                o.x = fmaxf(p0.x, 0.0f); o.y = fmaxf(p0.y, 0.0f);
                o.z = fmaxf(p1.x, 0.0f); o.w = fmaxf(p1.y, 0.0f);
                orow[j] = o;
            }
        }
    }
}

// ---------------- launch -----------------------------------------------------
extern "C" void kernel_launch(void* const* d_in, const int* in_sizes, int n_in,
                              void* d_out, int out_size) {
    const float* x  = nullptr;
    const void*  edge = nullptr;
    const float* Wl = nullptr;
    const float* Wr = nullptr;
    const float* bl = nullptr;
    for (int i = 0; i < n_in; i++) {
        int sz = in_sizes[i];
        if (sz == N_NODES * D)            x    = (const float*)d_in[i];
        else if (sz == 2 * N_EDGES)       edge = d_in[i];
        else if (sz == N_LAYERS * D * D) { if (!Wl) Wl = (const float*)d_in[i];
                                           else     Wr = (const float*)d_in[i]; }
        else if (sz == N_LAYERS * D)      bl   = (const float*)d_in[i];
    }
    float* out = (float*)d_out;

    static int smem_set = 0;
    if (!smem_set) {
        cudaFuncSetAttribute(gemm_kernel<1>,
                             cudaFuncAttributeMaxDynamicSharedMemorySize, SMEM_BYTES);
        cudaFuncSetAttribute(gemm_kernel<0>,
                             cudaFuncAttributeMaxDynamicSharedMemorySize, SMEM_BYTES);
        smem_set = 1;
    }

    init_kernel<<<(N_NODES + 255) / 256, 256>>>(edge);
    cvt16_kernel<<<(N_NODES * D / 2 + 255) / 256, 256>>>(x);
    histogram_kernel<<<(N_EDGES + 255) / 256, 256>>>(edge);
    scan1_kernel<<<NSB, SBLK>>>();
    scan3_kernel<<<NSB, SBLK>>>();
    scatter_kernel<<<(N_EDGES + 255) / 256, 256>>>(edge);

    int gblocks = (N_NODES + GNPB - 1) / GNPB;
    int mblocks = (N_NODES + NPB - 1) / NPB;

    __half* x16 = nullptr; __half* h16a = nullptr; __half* h16b = nullptr;
    __half* agg16 = nullptr;
    cudaGetSymbolAddress((void**)&x16, g_x16);
    cudaGetSymbolAddress((void**)&h16a, g_h16a);
    cudaGetSymbolAddress((void**)&h16b, g_h16b);
    cudaGetSymbolAddress((void**)&agg16, g_agg16);

    // layer 1: fp16 in (x16), fp16 out
    gather16_kernel<<<gblocks, GTPB>>>(x16, agg16);
    gemm_kernel<1><<<mblocks, TPB, SMEM_BYTES>>>(agg16, x16, h16a, Wl, bl, Wr, 0);
    // layer 2
    gather16_kernel<<<gblocks, GTPB>>>(h16a, agg16);
    gemm_kernel<1><<<mblocks, TPB, SMEM_BYTES>>>(agg16, h16a, h16b, Wl, bl, Wr, 1);
    // layer 3
    gather16_kernel<<<gblocks, GTPB>>>(h16b, agg16);
    gemm_kernel<1><<<mblocks, TPB, SMEM_BYTES>>>(agg16, h16b, h16a, Wl, bl, Wr, 2);
    // layer 4: fp16 in, fp32 out
    gather16_kernel<<<gblocks, GTPB>>>(h16a, agg16);
    gemm_kernel<0><<<mblocks, TPB, SMEM_BYTES>>>(agg16, h16a, out, Wl, bl, Wr, 3);
}

// round 9
// speedup vs baseline: 2.9107x; 2.3912x over previous
#include <cuda_runtime.h>
#include <cuda_fp16.h>
#include <math.h>

#define N_NODES 100000
#define N_EDGES 1250000
#define D 64
#define N_LAYERS 4

// ---- gemm kernel config ----
#define TPB 256                       // 8 warps, 1 M-tile (16 nodes) each
#define NPB 128                       // nodes per block
#define A_PITCH 136                   // halves; 272B row stride -> conflict-free LDSM
#define W_PITCH 72                    // halves; 144B row stride -> conflict-free LDSM
#define SA_HALVES (NPB * A_PITCH)     // 17408
#define SW_HALVES (128 * W_PITCH)     // 9216
#define SMEM_BYTES ((SA_HALVES + SW_HALVES) * 2 + D * 4)

// ---- gather kernel config ----
#define GTPB 256
#define GNPB 32

// ---- scan config ----
#define SBLK 1024
#define NSB ((N_NODES + SBLK - 1) / SBLK)   // 98

// ---------------- scratch (static device globals) ---------------------------
__device__ __half g_x16[N_NODES * D];
__device__ __half g_h16a[N_NODES * D];
__device__ __half g_h16b[N_NODES * D];
__device__ __half g_agg16[N_NODES * D];
__device__ int    g_counts[N_NODES];
__device__ int    g_rowptr[N_NODES + 1];
__device__ int    g_cursor[N_NODES];
__device__ int    g_csr[N_EDGES];
__device__ int    g_bsums[NSB];
__device__ int    g_is64;

// ---------------- mma helpers ------------------------------------------------
__device__ __forceinline__ unsigned s2u(const void* p) {
    return (unsigned)__cvta_generic_to_shared(p);
}
__device__ __forceinline__ void ldmx4(unsigned& a0, unsigned& a1,
                                      unsigned& a2, unsigned& a3, unsigned addr) {
    asm volatile("ldmatrix.sync.aligned.m8n8.x4.shared.b16 {%0,%1,%2,%3}, [%4];"
                 : "=r"(a0), "=r"(a1), "=r"(a2), "=r"(a3) : "r"(addr));
}
__device__ __forceinline__ void ldmx2t(unsigned& b0, unsigned& b1, unsigned addr) {
    asm volatile("ldmatrix.sync.aligned.m8n8.x2.trans.shared.b16 {%0,%1}, [%2];"
                 : "=r"(b0), "=r"(b1) : "r"(addr));
}
__device__ __forceinline__ void mma16816(float* c, unsigned a0, unsigned a1,
                                         unsigned a2, unsigned a3,
                                         unsigned b0, unsigned b1) {
    asm volatile(
        "mma.sync.aligned.m16n8k16.row.col.f32.f16.f16.f32 "
        "{%0,%1,%2,%3}, {%4,%5,%6,%7}, {%8,%9}, {%0,%1,%2,%3};"
        : "+f"(c[0]), "+f"(c[1]), "+f"(c[2]), "+f"(c[3])
        : "r"(a0), "r"(a1), "r"(a2), "r"(a3), "r"(b0), "r"(b1));
}

// ---------------- init: zero counts + dtype detection ------------------------
__global__ void init_kernel(const void* __restrict__ edge_raw) {
    int i = blockIdx.x * blockDim.x + threadIdx.x;
    if (i < N_NODES) g_counts[i] = 0;
    if (i == 0) {
        const long long* e64 = (const long long*)edge_raw;
        int ok64 = 1;
        #pragma unroll 8
        for (int t = 0; t < 64; t++) {
            long long v = e64[t];
            if (v < 0 || v >= N_NODES) ok64 = 0;
        }
        g_is64 = ok64;
    }
}

// ---------------- x -> fp16 --------------------------------------------------
__global__ void cvt16_kernel(const float* __restrict__ x) {
    int i = blockIdx.x * blockDim.x + threadIdx.x;
    if (i >= N_NODES * D / 2) return;
    float2 v = ((const float2*)x)[i];
    ((__half2*)g_x16)[i] = __floats2half2_rn(v.x, v.y);
}

__device__ __forceinline__ int load_edge(const void* edge_raw, long long idx, int is64) {
    if (is64) return (int)((const long long*)edge_raw)[idx];
    return ((const int*)edge_raw)[idx];
}

// ---------------- CSR build -------------------------------------------------
__global__ void histogram_kernel(const void* __restrict__ edge_raw) {
    int e = blockIdx.x * blockDim.x + threadIdx.x;
    if (e >= N_EDGES) return;
    int dst = load_edge(edge_raw, (long long)N_EDGES + e, g_is64);
    if (dst < 0 || dst >= N_NODES) return;
    atomicAdd(&g_counts[dst], 1);
}

__global__ __launch_bounds__(SBLK) void scan1_kernel() {
    __shared__ int wsum[32];
    int tid = threadIdx.x, lane = tid & 31, w = tid >> 5;
    int i = blockIdx.x * SBLK + tid;
    int v = (i < N_NODES) ? g_counts[i] : 0;
    int x = v;
    #pragma unroll
    for (int off = 1; off < 32; off <<= 1) {
        int y = __shfl_up_sync(0xffffffffu, x, off);
        if (lane >= off) x += y;
    }
    if (lane == 31) wsum[w] = x;
    __syncthreads();
    if (w == 0) {
        int s = wsum[lane];
        #pragma unroll
        for (int off = 1; off < 32; off <<= 1) {
            int y = __shfl_up_sync(0xffffffffu, s, off);
            if (lane >= off) s += y;
        }
        wsum[lane] = s;
    }
    __syncthreads();
    int incl = x + ((w > 0) ? wsum[w - 1] : 0);
    if (i < N_NODES) g_rowptr[i] = incl - v;
    if (tid == SBLK - 1) g_bsums[blockIdx.x] = incl;
}

__global__ __launch_bounds__(SBLK) void scan3_kernel() {
    __shared__ int sExcl[NSB];
    __shared__ int sTot;
    int tid = threadIdx.x;
    if (tid < 32) {
        int carry = 0;
        #pragma unroll
        for (int base = 0; base < NSB; base += 32) {
            int idx = base + tid;
            int v = (idx < NSB) ? g_bsums[idx] : 0;
            int x = v;
            #pragma unroll
            for (int off = 1; off < 32; off <<= 1) {
                int y = __shfl_up_sync(0xffffffffu, x, off);
                if (tid >= off) x += y;
            }
            if (idx < NSB) sExcl[idx] = carry + x - v;
            carry += __shfl_sync(0xffffffffu, x, 31);
        }
        if (tid == 0) sTot = carry;
    }
    __syncthreads();
    int i = blockIdx.x * SBLK + tid;
    if (i < N_NODES) {
        int r = g_rowptr[i] + sExcl[blockIdx.x];
        g_rowptr[i] = r;
        g_cursor[i] = r;
    }
    if (blockIdx.x == 0 && tid == 0) g_rowptr[N_NODES] = sTot;
}

__global__ void scatter_kernel(const void* __restrict__ edge_raw) {
    int e = blockIdx.x * blockDim.x + threadIdx.x;
    if (e >= N_EDGES) return;
    int is64 = g_is64;
    int src = load_edge(edge_raw, e, is64);
    int dst = load_edge(edge_raw, (long long)N_EDGES + e, is64);
    if (src < 0 || src >= N_NODES || dst < 0 || dst >= N_NODES) return;
    int pos = atomicAdd(&g_cursor[dst], 1);
    if (pos >= 0 && pos < N_EDGES) g_csr[pos] = src;
}

// ---------------- gather fp16: h16 -> agg16 ----------------------------------
__global__ __launch_bounds__(GTPB) void gather16_kernel(
    const __half* __restrict__ h_in, __half* __restrict__ agg_out)
{
    int tid = threadIdx.x;
    int warp = tid >> 5, lane = tid & 31;
    int sub = lane >> 3, dl = lane & 7;

    int node = blockIdx.x * GNPB + warp * 4 + sub;
    if (node >= N_NODES) return;
    int start = g_rowptr[node];
    int end   = g_rowptr[node + 1];

    const __half neginf = __ushort_as_half((unsigned short)0xFC00);
    __half2 m0 = __half2half2(neginf), m1 = m0, m2 = m0, m3 = m0;

    int j = start;
    #pragma unroll 1
    for (; j + 4 <= end; j += 4) {
        int s0 = g_csr[j];
        int s1 = g_csr[j + 1];
        int s2 = g_csr[j + 2];
        int s3 = g_csr[j + 3];
        uint4 v0 = *(const uint4*)(h_in + (size_t)s0 * D + dl * 8);
        uint4 v1 = *(const uint4*)(h_in + (size_t)s1 * D + dl * 8);
        uint4 v2 = *(const uint4*)(h_in + (size_t)s2 * D + dl * 8);
        uint4 v3 = *(const uint4*)(h_in + (size_t)s3 * D + dl * 8);
        m0 = __hmax2(m0, *(__half2*)&v0.x); m1 = __hmax2(m1, *(__half2*)&v0.y);
        m2 = __hmax2(m2, *(__half2*)&v0.z); m3 = __hmax2(m3, *(__half2*)&v0.w);
        m0 = __hmax2(m0, *(__half2*)&v1.x); m1 = __hmax2(m1, *(__half2*)&v1.y);
        m2 = __hmax2(m2, *(__half2*)&v1.z); m3 = __hmax2(m3, *(__half2*)&v1.w);
        m0 = __hmax2(m0, *(__half2*)&v2.x); m1 = __hmax2(m1, *(__half2*)&v2.y);
        m2 = __hmax2(m2, *(__half2*)&v2.z); m3 = __hmax2(m3, *(__half2*)&v2.w);
        m0 = __hmax2(m0, *(__half2*)&v3.x); m1 = __hmax2(m1, *(__half2*)&v3.y);
        m2 = __hmax2(m2, *(__half2*)&v3.z); m3 = __hmax2(m3, *(__half2*)&v3.w);
    }
    if (j + 2 <= end) {
        int s0 = g_csr[j];
        int s1 = g_csr[j + 1];
        uint4 v0 = *(const uint4*)(h_in + (size_t)s0 * D + dl * 8);
        uint4 v1 = *(const uint4*)(h_in + (size_t)s1 * D + dl * 8);
        m0 = __hmax2(m0, *(__half2*)&v0.x); m1 = __hmax2(m1, *(__half2*)&v0.y);
        m2 = __hmax2(m2, *(__half2*)&v0.z); m3 = __hmax2(m3, *(__half2*)&v0.w);
        m0 = __hmax2(m0, *(__half2*)&v1.x); m1 = __hmax2(m1, *(__half2*)&v1.y);
        m2 = __hmax2(m2, *(__half2*)&v1.z); m3 = __hmax2(m3, *(__half2*)&v1.w);
        j += 2;
    }
    if (j < end) {
        int s0 = g_csr[j];
        uint4 v0 = *(const uint4*)(h_in + (size_t)s0 * D + dl * 8);
        m0 = __hmax2(m0, *(__half2*)&v0.x); m1 = __hmax2(m1, *(__half2*)&v0.y);
        m2 = __hmax2(m2, *(__half2*)&v0.z); m3 = __hmax2(m3, *(__half2*)&v0.w);
    }
    if (start == end) {
        __half2 z = __half2half2(__ushort_as_half((unsigned short)0));
        m0 = z; m1 = z; m2 = z; m3 = z;
    }
    uint4 o;
    o.x = *(unsigned*)&m0; o.y = *(unsigned*)&m1;
    o.z = *(unsigned*)&m2; o.w = *(unsigned*)&m3;
    *(uint4*)(agg_out + (size_t)node * D + dl * 8) = o;
}

// ---------------- gemm (HMMA): out = relu([agg|h] @ [Wl;Wr] + bl) ------------
// Per block: C[128x64] = A[128x128]_f16 @ W[128x64]_f16 (+bias, relu).
// 8 warps, warp w owns M-tile rows [16w, 16w+16); 8 N-tiles x 8 K-steps of
// mma.m16n8k16 with fp32 accumulators.
template <int OUT16>
__global__ __launch_bounds__(TPB) void gemm_kernel(
    const __half* __restrict__ ag, const __half* __restrict__ hh,
    void* __restrict__ outp,
    const float* __restrict__ Wl, const float* __restrict__ bl,
    const float* __restrict__ Wr, int layer)
{
    extern __shared__ __half smem16[];
    __half* sA = smem16;                  // [128][A_PITCH]: cols 0-63 agg, 64-127 h
    __half* sW = smem16 + SA_HALVES;      // [128][W_PITCH]: rows 0-63 Wl, 64-127 Wr
    float*  sB = (float*)(smem16 + SA_HALVES + SW_HALVES);

    int tid = threadIdx.x;
    int blockBase = blockIdx.x * NPB;

    // stage W (fp32 -> fp16) : 128 rows x 16 float4
    {
        const float4* wl4 = (const float4*)(Wl + layer * D * D);
        const float4* wr4 = (const float4*)(Wr + layer * D * D);
        #pragma unroll
        for (int i = tid; i < 2048; i += TPB) {
            int row = i >> 4, c = i & 15;
            float4 v = (row < 64) ? wl4[row * 16 + c] : wr4[(row - 64) * 16 + c];
            __half2 h0 = __floats2half2_rn(v.x, v.y);
            __half2 h1 = __floats2half2_rn(v.z, v.w);
            uint2 u;
            u.x = *(unsigned*)&h0; u.y = *(unsigned*)&h1;
            *(uint2*)(sW + row * W_PITCH + c * 4) = u;
        }
        if (tid < D) sB[tid] = bl[layer * D + tid];
    }
    // stage A = [agg | h] (uint4 = 8 halves)
    #pragma unroll
    for (int i = tid; i < NPB * 8; i += TPB) {
        int row = i >> 3, c = i & 7;
        int node = blockBase + row;
        uint4 va = make_uint4(0, 0, 0, 0), vh = va;
        if (node < N_NODES) {
            va = ((const uint4*)(ag + (size_t)node * D))[c];
            vh = ((const uint4*)(hh + (size_t)node * D))[c];
        }
        *(uint4*)(sA + row * A_PITCH + c * 8)      = va;
        *(uint4*)(sA + row * A_PITCH + 64 + c * 8) = vh;
    }
    __syncthreads();

    int warp = tid >> 5, lane = tid & 31;
    float acc[8][4];
    #pragma unroll
    for (int n = 0; n < 8; n++) {
        acc[n][0] = 0.f; acc[n][1] = 0.f; acc[n][2] = 0.f; acc[n][3] = 0.f;
    }

    unsigned aBase = s2u(sA) + ((warp * 16 + (lane & 15)) * A_PITCH + (lane >> 4) * 8) * 2;
    unsigned bBase = s2u(sW) + ((lane & 15) * W_PITCH) * 2;

    #pragma unroll
    for (int kk = 0; kk < 8; kk++) {
        unsigned a0, a1, a2, a3;
        ldmx4(a0, a1, a2, a3, aBase + kk * 16 * 2);
        unsigned brow = bBase + kk * 16 * W_PITCH * 2;
        #pragma unroll
        for (int n = 0; n < 8; n++) {
            unsigned b0, b1;
            ldmx2t(b0, b1, brow + n * 8 * 2);
            mma16816(acc[n], a0, a1, a2, a3, b0, b1);
        }
    }

    // epilogue: bias + relu
    int g = lane >> 2, t = lane & 3;
    if (OUT16) {
        __syncthreads();                  // all reads of sA/sW done; reuse sA as sC
        #pragma unroll
        for (int n = 0; n < 8; n++) {
            int col = n * 8 + t * 2;
            float bx = sB[col], by = sB[col + 1];
            __half2 h01 = __floats2half2_rn(fmaxf(acc[n][0] + bx, 0.f),
                                            fmaxf(acc[n][1] + by, 0.f));
            __half2 h23 = __floats2half2_rn(fmaxf(acc[n][2] + bx, 0.f),
                                            fmaxf(acc[n][3] + by, 0.f));
            *(__half2*)(sA + (warp * 16 + g)     * A_PITCH + col) = h01;
            *(__half2*)(sA + (warp * 16 + g + 8) * A_PITCH + col) = h23;
        }
        __syncthreads();
        __half* o16 = (__half*)outp;
        #pragma unroll
        for (int i = tid; i < NPB * 8; i += TPB) {
            int row = i >> 3, c = i & 7;
            int node = blockBase + row;
            if (node < N_NODES)
                *(uint4*)(o16 + (size_t)node * D + c * 8) =
                    *(uint4*)(sA + row * A_PITCH + c * 8);
        }
    } else {
        float* o32 = (float*)outp;
        int row0 = blockBase + warp * 16 + g;
        int row1 = row0 + 8;
        #pragma unroll
        for (int n = 0; n < 8; n++) {
            int col = n * 8 + t * 2;
            float bx = sB[col], by = sB[col + 1];
            if (row0 < N_NODES) {
                float2 v = make_float2(fmaxf(acc[n][0] + bx, 0.f),
                                       fmaxf(acc[n][1] + by, 0.f));
                *(float2*)(o32 + (size_t)row0 * D + col) = v;
            }
            if (row1 < N_NODES) {
                float2 v = make_float2(fmaxf(acc[n][2] + bx, 0.f),
                                       fmaxf(acc[n][3] + by, 0.f));
                *(float2*)(o32 + (size_t)row1 * D + col) = v;
            }
        }
    }
}

// ---------------- launch -----------------------------------------------------
extern "C" void kernel_launch(void* const* d_in, const int* in_sizes, int n_in,
                              void* d_out, int out_size) {
    const float* x  = nullptr;
    const void*  edge = nullptr;
    const float* Wl = nullptr;
    const float* Wr = nullptr;
    const float* bl = nullptr;
    for (int i = 0; i < n_in; i++) {
        int sz = in_sizes[i];
        if (sz == N_NODES * D)            x    = (const float*)d_in[i];
        else if (sz == 2 * N_EDGES)       edge = d_in[i];
        else if (sz == N_LAYERS * D * D) { if (!Wl) Wl = (const float*)d_in[i];
                                           else     Wr = (const float*)d_in[i]; }
        else if (sz == N_LAYERS * D)      bl   = (const float*)d_in[i];
    }
    float* out = (float*)d_out;

    static int smem_set = 0;
    if (!smem_set) {
        cudaFuncSetAttribute(gemm_kernel<1>,
                             cudaFuncAttributeMaxDynamicSharedMemorySize, SMEM_BYTES);
        cudaFuncSetAttribute(gemm_kernel<0>,
                             cudaFuncAttributeMaxDynamicSharedMemorySize, SMEM_BYTES);
        smem_set = 1;
    }

    init_kernel<<<(N_NODES + 255) / 256, 256>>>(edge);
    cvt16_kernel<<<(N_NODES * D / 2 + 255) / 256, 256>>>(x);
    histogram_kernel<<<(N_EDGES + 255) / 256, 256>>>(edge);
    scan1_kernel<<<NSB, SBLK>>>();
    scan3_kernel<<<NSB, SBLK>>>();
    scatter_kernel<<<(N_EDGES + 255) / 256, 256>>>(edge);

    int gblocks = (N_NODES + GNPB - 1) / GNPB;
    int mblocks = (N_NODES + NPB - 1) / NPB;

    __half* x16 = nullptr; __half* h16a = nullptr; __half* h16b = nullptr;
    __half* agg16 = nullptr;
    cudaGetSymbolAddress((void**)&x16, g_x16);
    cudaGetSymbolAddress((void**)&h16a, g_h16a);
    cudaGetSymbolAddress((void**)&h16b, g_h16b);
    cudaGetSymbolAddress((void**)&agg16, g_agg16);

    // layer 1
    gather16_kernel<<<gblocks, GTPB>>>(x16, agg16);
    gemm_kernel<1><<<mblocks, TPB, SMEM_BYTES>>>(agg16, x16, h16a, Wl, bl, Wr, 0);
    // layer 2
    gather16_kernel<<<gblocks, GTPB>>>(h16a, agg16);
    gemm_kernel<1><<<mblocks, TPB, SMEM_BYTES>>>(agg16, h16a, h16b, Wl, bl, Wr, 1);
    // layer 3
    gather16_kernel<<<gblocks, GTPB>>>(h16b, agg16);
    gemm_kernel<1><<<mblocks, TPB, SMEM_BYTES>>>(agg16, h16b, h16a, Wl, bl, Wr, 2);
    // layer 4: fp32 out
    gather16_kernel<<<gblocks, GTPB>>>(h16a, agg16);
    gemm_kernel<0><<<mblocks, TPB, SMEM_BYTES>>>(agg16, h16a, out, Wl, bl, Wr, 3);
}

// round 10
// speedup vs baseline: 2.9119x; 1.0004x over previous
#include <cuda_runtime.h>
#include <cuda_fp16.h>
#include <math.h>

#define N_NODES 100000
#define N_EDGES 1250000
#define D 64
#define N_LAYERS 4

// ---- gemm kernel config ----
#define TPB 256                       // 8 warps, 1 M-tile (16 nodes) each
#define NPB 128                       // nodes per block
#define A_PITCH 136                   // halves; 272B row stride -> conflict-free LDSM
#define W_PITCH 72                    // halves; 144B row stride -> conflict-free LDSM
#define SA_HALVES (NPB * A_PITCH)     // 17408
#define SW_HALVES (128 * W_PITCH)     // 9216
#define SMEM_BYTES ((SA_HALVES + SW_HALVES) * 2 + D * 4)

// ---- gather kernel config ----
#define GTPB 256
#define GNPB 32

// ---- scan config ----
#define SBLK 1024
#define NSB ((N_NODES + SBLK - 1) / SBLK)   // 98

// ---------------- scratch (static device globals) ---------------------------
__device__ __half g_x16[N_NODES * D];
__device__ __half g_h16a[N_NODES * D];
__device__ __half g_h16b[N_NODES * D];
__device__ __half g_agg16[N_NODES * D];
__device__ int    g_counts[N_NODES];
__device__ int    g_rowptr[N_NODES + 1];
__device__ int    g_cursor[N_NODES];
__device__ int    g_csr[N_EDGES];
__device__ int    g_bsums[NSB];
__device__ int    g_is64;

// ---------------- mma helpers ------------------------------------------------
__device__ __forceinline__ unsigned s2u(const void* p) {
    return (unsigned)__cvta_generic_to_shared(p);
}
__device__ __forceinline__ void ldmx4(unsigned& a0, unsigned& a1,
                                      unsigned& a2, unsigned& a3, unsigned addr) {
    asm volatile("ldmatrix.sync.aligned.m8n8.x4.shared.b16 {%0,%1,%2,%3}, [%4];"
                 : "=r"(a0), "=r"(a1), "=r"(a2), "=r"(a3) : "r"(addr));
}
__device__ __forceinline__ void ldmx2t(unsigned& b0, unsigned& b1, unsigned addr) {
    asm volatile("ldmatrix.sync.aligned.m8n8.x2.trans.shared.b16 {%0,%1}, [%2];"
                 : "=r"(b0), "=r"(b1) : "r"(addr));
}
__device__ __forceinline__ void mma16816(float* c, unsigned a0, unsigned a1,
                                         unsigned a2, unsigned a3,
                                         unsigned b0, unsigned b1) {
    asm volatile(
        "mma.sync.aligned.m16n8k16.row.col.f32.f16.f16.f32 "
        "{%0,%1,%2,%3}, {%4,%5,%6,%7}, {%8,%9}, {%0,%1,%2,%3};"
        : "+f"(c[0]), "+f"(c[1]), "+f"(c[2]), "+f"(c[3])
        : "r"(a0), "r"(a1), "r"(a2), "r"(a3), "r"(b0), "r"(b1));
}

// ---------------- init: zero counts + dtype detect + x->fp16 -----------------
__global__ void init_cvt_kernel(const void* __restrict__ edge_raw,
                                const float* __restrict__ x) {
    int i = blockIdx.x * blockDim.x + threadIdx.x;
    if (i < N_NODES * D / 2) {
        float2 v = ((const float2*)x)[i];
        ((__half2*)g_x16)[i] = __floats2half2_rn(v.x, v.y);
    }
    if (i < N_NODES) g_counts[i] = 0;
    if (i == 0) {
        const long long* e64 = (const long long*)edge_raw;
        int ok64 = 1;
        #pragma unroll 8
        for (int t = 0; t < 64; t++) {
            long long v = e64[t];
            if (v < 0 || v >= N_NODES) ok64 = 0;
        }
        g_is64 = ok64;
    }
}

// ---------------- CSR build (2 edges per thread) -----------------------------
__global__ void histogram_kernel(const void* __restrict__ edge_raw) {
    int p = blockIdx.x * blockDim.x + threadIdx.x;      // edge pair index
    int e = p * 2;
    if (e >= N_EDGES) return;
    int d0, d1;
    if (g_is64) {
        longlong2 v = ((const longlong2*)edge_raw)[N_EDGES / 2 + p];
        d0 = (int)v.x; d1 = (int)v.y;
    } else {
        int2 v = ((const int2*)edge_raw)[N_EDGES / 2 + p];
        d0 = v.x; d1 = v.y;
    }
    if (d0 >= 0 && d0 < N_NODES) atomicAdd(&g_counts[d0], 1);
    if (e + 1 < N_EDGES && d1 >= 0 && d1 < N_NODES) atomicAdd(&g_counts[d1], 1);
}

__global__ __launch_bounds__(SBLK) void scan1_kernel() {
    __shared__ int wsum[32];
    int tid = threadIdx.x, lane = tid & 31, w = tid >> 5;
    int i = blockIdx.x * SBLK + tid;
    int v = (i < N_NODES) ? g_counts[i] : 0;
    int x = v;
    #pragma unroll
    for (int off = 1; off < 32; off <<= 1) {
        int y = __shfl_up_sync(0xffffffffu, x, off);
        if (lane >= off) x += y;
    }
    if (lane == 31) wsum[w] = x;
    __syncthreads();
    if (w == 0) {
        int s = wsum[lane];
        #pragma unroll
        for (int off = 1; off < 32; off <<= 1) {
            int y = __shfl_up_sync(0xffffffffu, s, off);
            if (lane >= off) s += y;
        }
        wsum[lane] = s;
    }
    __syncthreads();
    int incl = x + ((w > 0) ? wsum[w - 1] : 0);
    if (i < N_NODES) g_rowptr[i] = incl - v;
    if (tid == SBLK - 1) g_bsums[blockIdx.x] = incl;
}

__global__ __launch_bounds__(SBLK) void scan3_kernel() {
    __shared__ int sExcl[NSB];
    __shared__ int sTot;
    int tid = threadIdx.x;
    if (tid < 32) {
        int carry = 0;
        #pragma unroll
        for (int base = 0; base < NSB; base += 32) {
            int idx = base + tid;
            int v = (idx < NSB) ? g_bsums[idx] : 0;
            int x = v;
            #pragma unroll
            for (int off = 1; off < 32; off <<= 1) {
                int y = __shfl_up_sync(0xffffffffu, x, off);
                if (tid >= off) x += y;
            }
            if (idx < NSB) sExcl[idx] = carry + x - v;
            carry += __shfl_sync(0xffffffffu, x, 31);
        }
        if (tid == 0) sTot = carry;
    }
    __syncthreads();
    int i = blockIdx.x * SBLK + tid;
    if (i < N_NODES) {
        int r = g_rowptr[i] + sExcl[blockIdx.x];
        g_rowptr[i] = r;
        g_cursor[i] = r;
    }
    if (blockIdx.x == 0 && tid == 0) g_rowptr[N_NODES] = sTot;
}

__global__ void scatter_kernel(const void* __restrict__ edge_raw) {
    int p = blockIdx.x * blockDim.x + threadIdx.x;      // edge pair index
    int e = p * 2;
    if (e >= N_EDGES) return;
    int s0, s1, d0, d1;
    if (g_is64) {
        longlong2 sv = ((const longlong2*)edge_raw)[p];
        longlong2 dv = ((const longlong2*)edge_raw)[N_EDGES / 2 + p];
        s0 = (int)sv.x; s1 = (int)sv.y; d0 = (int)dv.x; d1 = (int)dv.y;
    } else {
        int2 sv = ((const int2*)edge_raw)[p];
        int2 dv = ((const int2*)edge_raw)[N_EDGES / 2 + p];
        s0 = sv.x; s1 = sv.y; d0 = dv.x; d1 = dv.y;
    }
    if (s0 >= 0 && s0 < N_NODES && d0 >= 0 && d0 < N_NODES) {
        int pos = atomicAdd(&g_cursor[d0], 1);
        if (pos >= 0 && pos < N_EDGES) g_csr[pos] = s0;
    }
    if (e + 1 < N_EDGES && s1 >= 0 && s1 < N_NODES && d1 >= 0 && d1 < N_NODES) {
        int pos = atomicAdd(&g_cursor[d1], 1);
        if (pos >= 0 && pos < N_EDGES) g_csr[pos] = s1;
    }
}

// ---------------- gather fp16: h16 -> agg16 ----------------------------------
// 8-lane subgroup per node; one LDG.128 per lane per edge; 8-edge main loop
// (8 independent loads in flight per lane), 4/2/1 remainders.
#define GMAX2(v) do { \
    m0 = __hmax2(m0, *(__half2*)&(v).x); m1 = __hmax2(m1, *(__half2*)&(v).y); \
    m2 = __hmax2(m2, *(__half2*)&(v).z); m3 = __hmax2(m3, *(__half2*)&(v).w); } while (0)

__global__ __launch_bounds__(GTPB) void gather16_kernel(
    const __half* __restrict__ h_in, __half* __restrict__ agg_out)
{
    int tid = threadIdx.x;
    int warp = tid >> 5, lane = tid & 31;
    int sub = lane >> 3, dl = lane & 7;

    int node = blockIdx.x * GNPB + warp * 4 + sub;
    if (node >= N_NODES) return;
    int start = g_rowptr[node];
    int end   = g_rowptr[node + 1];

    const __half neginf = __ushort_as_half((unsigned short)0xFC00);
    __half2 m0 = __half2half2(neginf), m1 = m0, m2 = m0, m3 = m0;

    int j = start;
    #pragma unroll 1
    for (; j + 8 <= end; j += 8) {
        int s0 = g_csr[j],     s1 = g_csr[j + 1];
        int s2 = g_csr[j + 2], s3 = g_csr[j + 3];
        int s4 = g_csr[j + 4], s5 = g_csr[j + 5];
        int s6 = g_csr[j + 6], s7 = g_csr[j + 7];
        uint4 v0 = *(const uint4*)(h_in + (size_t)s0 * D + dl * 8);
        uint4 v1 = *(const uint4*)(h_in + (size_t)s1 * D + dl * 8);
        uint4 v2 = *(const uint4*)(h_in + (size_t)s2 * D + dl * 8);
        uint4 v3 = *(const uint4*)(h_in + (size_t)s3 * D + dl * 8);
        uint4 v4 = *(const uint4*)(h_in + (size_t)s4 * D + dl * 8);
        uint4 v5 = *(const uint4*)(h_in + (size_t)s5 * D + dl * 8);
        uint4 v6 = *(const uint4*)(h_in + (size_t)s6 * D + dl * 8);
        uint4 v7 = *(const uint4*)(h_in + (size_t)s7 * D + dl * 8);
        GMAX2(v0); GMAX2(v1); GMAX2(v2); GMAX2(v3);
        GMAX2(v4); GMAX2(v5); GMAX2(v6); GMAX2(v7);
    }
    if (j + 4 <= end) {
        int s0 = g_csr[j],     s1 = g_csr[j + 1];
        int s2 = g_csr[j + 2], s3 = g_csr[j + 3];
        uint4 v0 = *(const uint4*)(h_in + (size_t)s0 * D + dl * 8);
        uint4 v1 = *(const uint4*)(h_in + (size_t)s1 * D + dl * 8);
        uint4 v2 = *(const uint4*)(h_in + (size_t)s2 * D + dl * 8);
        uint4 v3 = *(const uint4*)(h_in + (size_t)s3 * D + dl * 8);
        GMAX2(v0); GMAX2(v1); GMAX2(v2); GMAX2(v3);
        j += 4;
    }
    if (j + 2 <= end) {
        int s0 = g_csr[j], s1 = g_csr[j + 1];
        uint4 v0 = *(const uint4*)(h_in + (size_t)s0 * D + dl * 8);
        uint4 v1 = *(const uint4*)(h_in + (size_t)s1 * D + dl * 8);
        GMAX2(v0); GMAX2(v1);
        j += 2;
    }
    if (j < end) {
        int s0 = g_csr[j];
        uint4 v0 = *(const uint4*)(h_in + (size_t)s0 * D + dl * 8);
        GMAX2(v0);
    }
    if (start == end) {
        __half2 z = __half2half2(__ushort_as_half((unsigned short)0));
        m0 = z; m1 = z; m2 = z; m3 = z;
    }
    uint4 o;
    o.x = *(unsigned*)&m0; o.y = *(unsigned*)&m1;
    o.z = *(unsigned*)&m2; o.w = *(unsigned*)&m3;
    *(uint4*)(agg_out + (size_t)node * D + dl * 8) = o;
}

// ---------------- gemm (HMMA): out = relu([agg|h] @ [Wl;Wr] + bl) ------------
template <int OUT16>
__global__ __launch_bounds__(TPB) void gemm_kernel(
    const __half* __restrict__ ag, const __half* __restrict__ hh,
    void* __restrict__ outp,
    const float* __restrict__ Wl, const float* __restrict__ bl,
    const float* __restrict__ Wr, int layer)
{
    extern __shared__ __half smem16[];
    __half* sA = smem16;                  // [128][A_PITCH]: cols 0-63 agg, 64-127 h
    __half* sW = smem16 + SA_HALVES;      // [128][W_PITCH]: rows 0-63 Wl, 64-127 Wr
    float*  sB = (float*)(smem16 + SA_HALVES + SW_HALVES);

    int tid = threadIdx.x;
    int blockBase = blockIdx.x * NPB;

    // stage W (fp32 -> fp16)
    {
        const float4* wl4 = (const float4*)(Wl + layer * D * D);
        const float4* wr4 = (const float4*)(Wr + layer * D * D);
        #pragma unroll
        for (int i = tid; i < 2048; i += TPB) {
            int row = i >> 4, c = i & 15;
            float4 v = (row < 64) ? wl4[row * 16 + c] : wr4[(row - 64) * 16 + c];
            __half2 h0 = __floats2half2_rn(v.x, v.y);
            __half2 h1 = __floats2half2_rn(v.z, v.w);
            uint2 u;
            u.x = *(unsigned*)&h0; u.y = *(unsigned*)&h1;
            *(uint2*)(sW + row * W_PITCH + c * 4) = u;
        }
        if (tid < D) sB[tid] = bl[layer * D + tid];
    }
    // stage A = [agg | h]
    #pragma unroll
    for (int i = tid; i < NPB * 8; i += TPB) {
        int row = i >> 3, c = i & 7;
        int node = blockBase + row;
        uint4 va = make_uint4(0, 0, 0, 0), vh = va;
        if (node < N_NODES) {
            va = ((const uint4*)(ag + (size_t)node * D))[c];
            vh = ((const uint4*)(hh + (size_t)node * D))[c];
        }
        *(uint4*)(sA + row * A_PITCH + c * 8)      = va;
        *(uint4*)(sA + row * A_PITCH + 64 + c * 8) = vh;
    }
    __syncthreads();

    int warp = tid >> 5, lane = tid & 31;
    float acc[8][4];
    #pragma unroll
    for (int n = 0; n < 8; n++) {
        acc[n][0] = 0.f; acc[n][1] = 0.f; acc[n][2] = 0.f; acc[n][3] = 0.f;
    }

    unsigned aBase = s2u(sA) + ((warp * 16 + (lane & 15)) * A_PITCH + (lane >> 4) * 8) * 2;
    unsigned bBase = s2u(sW) + ((lane & 15) * W_PITCH) * 2;

    #pragma unroll
    for (int kk = 0; kk < 8; kk++) {
        unsigned a0, a1, a2, a3;
        ldmx4(a0, a1, a2, a3, aBase + kk * 16 * 2);
        unsigned brow = bBase + kk * 16 * W_PITCH * 2;
        #pragma unroll
        for (int n = 0; n < 8; n++) {
            unsigned b0, b1;
            ldmx2t(b0, b1, brow + n * 8 * 2);
            mma16816(acc[n], a0, a1, a2, a3, b0, b1);
        }
    }

    // epilogue: bias + relu
    int g = lane >> 2, t = lane & 3;
    if (OUT16) {
        __syncthreads();                  // reuse sA as sC
        #pragma unroll
        for (int n = 0; n < 8; n++) {
            int col = n * 8 + t * 2;
            float bx = sB[col], by = sB[col + 1];
            __half2 h01 = __floats2half2_rn(fmaxf(acc[n][0] + bx, 0.f),
                                            fmaxf(acc[n][1] + by, 0.f));
            __half2 h23 = __floats2half2_rn(fmaxf(acc[n][2] + bx, 0.f),
                                            fmaxf(acc[n][3] + by, 0.f));
            *(__half2*)(sA + (warp * 16 + g)     * A_PITCH + col) = h01;
            *(__half2*)(sA + (warp * 16 + g + 8) * A_PITCH + col) = h23;
        }
        __syncthreads();
        __half* o16 = (__half*)outp;
        #pragma unroll
        for (int i = tid; i < NPB * 8; i += TPB) {
            int row = i >> 3, c = i & 7;
            int node = blockBase + row;
            if (node < N_NODES)
                *(uint4*)(o16 + (size_t)node * D + c * 8) =
                    *(uint4*)(sA + row * A_PITCH + c * 8);
        }
    } else {
        float* o32 = (float*)outp;
        int row0 = blockBase + warp * 16 + g;
        int row1 = row0 + 8;
        #pragma unroll
        for (int n = 0; n < 8; n++) {
            int col = n * 8 + t * 2;
            float bx = sB[col], by = sB[col + 1];
            if (row0 < N_NODES) {
                float2 v = make_float2(fmaxf(acc[n][0] + bx, 0.f),
                                       fmaxf(acc[n][1] + by, 0.f));
                *(float2*)(o32 + (size_t)row0 * D + col) = v;
            }
            if (row1 < N_NODES) {
                float2 v = make_float2(fmaxf(acc[n][2] + bx, 0.f),
                                       fmaxf(acc[n][3] + by, 0.f));
                *(float2*)(o32 + (size_t)row1 * D + col) = v;
            }
        }
    }
}

// ---------------- launch -----------------------------------------------------
extern "C" void kernel_launch(void* const* d_in, const int* in_sizes, int n_in,
                              void* d_out, int out_size) {
    const float* x  = nullptr;
    const void*  edge = nullptr;
    const float* Wl = nullptr;
    const float* Wr = nullptr;
    const float* bl = nullptr;
    for (int i = 0; i < n_in; i++) {
        int sz = in_sizes[i];
        if (sz == N_NODES * D)            x    = (const float*)d_in[i];
        else if (sz == 2 * N_EDGES)       edge = d_in[i];
        else if (sz == N_LAYERS * D * D) { if (!Wl) Wl = (const float*)d_in[i];
                                           else     Wr = (const float*)d_in[i]; }
        else if (sz == N_LAYERS * D)      bl   = (const float*)d_in[i];
    }
    float* out = (float*)d_out;

    static int smem_set = 0;
    if (!smem_set) {
        cudaFuncSetAttribute(gemm_kernel<1>,
                             cudaFuncAttributeMaxDynamicSharedMemorySize, SMEM_BYTES);
        cudaFuncSetAttribute(gemm_kernel<0>,
                             cudaFuncAttributeMaxDynamicSharedMemorySize, SMEM_BYTES);
        smem_set = 1;
    }

    init_cvt_kernel<<<(N_NODES * D / 2 + 255) / 256, 256>>>(edge, x);
    histogram_kernel<<<(N_EDGES / 2 + 255) / 256, 256>>>(edge);
    scan1_kernel<<<NSB, SBLK>>>();
    scan3_kernel<<<NSB, SBLK>>>();
    scatter_kernel<<<(N_EDGES / 2 + 255) / 256, 256>>>(edge);

    int gblocks = (N_NODES + GNPB - 1) / GNPB;
    int mblocks = (N_NODES + NPB - 1) / NPB;

    __half* x16 = nullptr; __half* h16a = nullptr; __half* h16b = nullptr;
    __half* agg16 = nullptr;
    cudaGetSymbolAddress((void**)&x16, g_x16);
    cudaGetSymbolAddress((void**)&h16a, g_h16a);
    cudaGetSymbolAddress((void**)&h16b, g_h16b);
    cudaGetSymbolAddress((void**)&agg16, g_agg16);

    // layer 1
    gather16_kernel<<<gblocks, GTPB>>>(x16, agg16);
    gemm_kernel<1><<<mblocks, TPB, SMEM_BYTES>>>(agg16, x16, h16a, Wl, bl, Wr, 0);
    // layer 2
    gather16_kernel<<<gblocks, GTPB>>>(h16a, agg16);
    gemm_kernel<1><<<mblocks, TPB, SMEM_BYTES>>>(agg16, h16a, h16b, Wl, bl, Wr, 1);
    // layer 3
    gather16_kernel<<<gblocks, GTPB>>>(h16b, agg16);
    gemm_kernel<1><<<mblocks, TPB, SMEM_BYTES>>>(agg16, h16b, h16a, Wl, bl, Wr, 2);
    // layer 4: fp32 out
    gather16_kernel<<<gblocks, GTPB>>>(h16a, agg16);
    gemm_kernel<0><<<mblocks, TPB, SMEM_BYTES>>>(agg16, h16a, out, Wl, bl, Wr, 3);
}